// round 3
// baseline (speedup 1.0000x reference)
#include <cuda_runtime.h>
#include <cuda_bf16.h>

#define Bb 2
#define Tt 2048
#define Cc 1024
#define Hh 16
#define HD 64

// Scratch (allocation-free rule: __device__ globals)
__device__ float g_q3[(size_t)Bb*Hh*Tt*3];           // (b,h,t,3)
__device__ float g_ka[(size_t)Bb*Hh*Tt*3];           // (b,h,t,3) transformed keys
__device__ float g_v [(size_t)Bb*Hh*Tt*HD];          // (b,h,t,64)
__device__ float g_ao[(size_t)Bb*Tt*Cc];             // (b,t,c) attention output

// ---------------------------------------------------------------------------
// Kernel 1: QK projection + fold (scale*I + d d^T) into K.
// One block = 8 rows of x. 128 threads; threads 0..95 compute the 96 columns.
// ---------------------------------------------------------------------------
__global__ void proj_qk_kernel(const float* __restrict__ x,
                               const float* __restrict__ wq,
                               const float* __restrict__ wk,
                               const float* __restrict__ dirs,
                               const float* __restrict__ scale_p) {
    __shared__ float xs[8][Cc];
    __shared__ float sk[8][48];
    const int tid = threadIdx.x;                 // 128
    const int rowBase = blockIdx.x * 8;

    // Load 8 rows of x (8*1024 floats) via float4
    {
        const float4* src = (const float4*)(x + (size_t)rowBase * Cc);
        float4* dst = (float4*)&xs[0][0];
        #pragma unroll
        for (int i = tid; i < 8 * Cc / 4; i += 128) dst[i] = src[i];
    }
    __syncthreads();

    if (tid < 96) {
        const int col = tid % 48;
        const float* __restrict__ w = (tid < 48) ? wq : wk;
        float acc[8];
        #pragma unroll
        for (int r = 0; r < 8; r++) acc[r] = 0.f;
        for (int i = 0; i < Cc; i += 4) {
            float w0 = w[(i + 0) * 48 + col];
            float w1 = w[(i + 1) * 48 + col];
            float w2 = w[(i + 2) * 48 + col];
            float w3 = w[(i + 3) * 48 + col];
            #pragma unroll
            for (int r = 0; r < 8; r++) {
                float4 xv = *(const float4*)&xs[r][i];
                acc[r] = fmaf(xv.x, w0, fmaf(xv.y, w1, fmaf(xv.z, w2, fmaf(xv.w, w3, acc[r]))));
            }
        }
        const int h = col / 3, d = col % 3;
        if (tid < 48) {
            #pragma unroll
            for (int r = 0; r < 8; r++) {
                int row = rowBase + r;
                int b = row / Tt, t = row % Tt;
                g_q3[(((size_t)b * Hh + h) * Tt + t) * 3 + d] = acc[r];
            }
        } else {
            #pragma unroll
            for (int r = 0; r < 8; r++) sk[r][col] = acc[r];
        }
    }
    __syncthreads();

    // Transform K: ka = scale*k + d*(d.k).  128 threads = 8 rows x 16 heads.
    {
        const int r = tid >> 4, h = tid & 15;
        const float d0 = dirs[h * 3 + 0], d1 = dirs[h * 3 + 1], d2 = dirs[h * 3 + 2];
        const float sc = scale_p[0];
        const float k0 = sk[r][3 * h + 0], k1 = sk[r][3 * h + 1], k2 = sk[r][3 * h + 2];
        const float dot = d0 * k0 + d1 * k1 + d2 * k2;
        int row = rowBase + r;
        int b = row / Tt, t = row % Tt;
        size_t base = (((size_t)b * Hh + h) * Tt + t) * 3;
        g_ka[base + 0] = sc * k0 + d0 * dot;
        g_ka[base + 1] = sc * k1 + d1 * dot;
        g_ka[base + 2] = sc * k2 + d2 * dot;
    }
}

// ---------------------------------------------------------------------------
// Kernel 2/4: fp32 GEMM, M=4096 N=1024 K=1024, 64x64 tile, BK=16, 256 threads,
// 4x4 micro-tile. SCATTER=true rearranges output into (b,h,t,64) for V.
// ---------------------------------------------------------------------------
template <bool SCATTER>
__global__ void gemm_kernel(const float* __restrict__ A,
                            const float* __restrict__ Bw,
                            float* __restrict__ Cout) {
    const int M = Bb * Tt;      // 4096
    const int N = Cc;           // 1024
    const int K = Cc;           // 1024
    __shared__ float As[16][64];   // k-major (transposed) for lds.128 in compute
    __shared__ float Bs[16][64];

    const int tx = threadIdx.x % 16;
    const int ty = threadIdx.x / 16;
    const int rowBase = blockIdx.y * 64;
    const int colBase = blockIdx.x * 64;

    float acc[4][4];
    #pragma unroll
    for (int i = 0; i < 4; i++)
        #pragma unroll
        for (int j = 0; j < 4; j++) acc[i][j] = 0.f;

    const int idx = threadIdx.x * 4;
    const int ar = idx >> 4, ac = idx & 15;      // A-tile: 64 rows x 16 cols
    const int br = idx >> 6, bc = idx & 63;      // B-tile: 16 rows x 64 cols

    for (int k0 = 0; k0 < K; k0 += 16) {
        float4 a = *(const float4*)&A[(size_t)(rowBase + ar) * K + k0 + ac];
        As[ac + 0][ar] = a.x;
        As[ac + 1][ar] = a.y;
        As[ac + 2][ar] = a.z;
        As[ac + 3][ar] = a.w;
        *(float4*)&Bs[br][bc] = *(const float4*)&Bw[(size_t)(k0 + br) * N + colBase + bc];
        __syncthreads();
        #pragma unroll
        for (int kk = 0; kk < 16; kk++) {
            float4 ra = *(const float4*)&As[kk][ty * 4];
            float4 rb = *(const float4*)&Bs[kk][tx * 4];
            float av[4] = {ra.x, ra.y, ra.z, ra.w};
            float bv[4] = {rb.x, rb.y, rb.z, rb.w};
            #pragma unroll
            for (int i = 0; i < 4; i++)
                #pragma unroll
                for (int j = 0; j < 4; j++)
                    acc[i][j] = fmaf(av[i], bv[j], acc[i][j]);
        }
        __syncthreads();
    }

    #pragma unroll
    for (int i = 0; i < 4; i++) {
        int m = rowBase + ty * 4 + i;
        #pragma unroll
        for (int j = 0; j < 4; j++) {
            int n = colBase + tx * 4 + j;
            if (SCATTER) {
                int b = m >> 11, t = m & (Tt - 1);
                int h = n >> 6, d = n & (HD - 1);
                Cout[(((size_t)b * Hh + h) * Tt + t) * HD + d] = acc[i][j];
            } else {
                Cout[(size_t)m * N + n] = acc[i][j];
            }
        }
    }
}

// ---------------------------------------------------------------------------
// Kernel 3: causal flash attention, d_qk=3 (bias pre-folded into ka), d_v=64.
// 1 thread = 1 query. 128-query blocks, 128-key tiles.
// Per-tile Cauchy-Schwarz bound |q||k|max keeps the inner loop branch-free.
// ---------------------------------------------------------------------------
__global__ void attn_kernel() {
    __shared__ float4 skv[128];        // key tile: (k0,k1,k2,pad)
    __shared__ float  sv[128][HD];     // value tile 32KB
    __shared__ float  red[4];

    const int tid = threadIdx.x;       // 128
    const int bh  = blockIdx.y;        // b*H + h
    const int qt  = blockIdx.x;
    const int qi  = qt * 128 + tid;

    const float* qp = g_q3 + ((size_t)bh * Tt + qi) * 3;
    const float q0 = qp[0], q1 = qp[1], q2 = qp[2];
    const float qn = sqrtf(q0 * q0 + q1 * q1 + q2 * q2);

    float m = -1e30f, l = 0.f;
    float acc[HD];
    #pragma unroll
    for (int d = 0; d < HD; d++) acc[d] = 0.f;

    const int kmax = qt * 128 + 127;
    const float* kb = g_ka + (size_t)bh * Tt * 3;
    const float* vb = g_v  + (size_t)bh * Tt * HD;

    for (int s0 = 0; s0 <= kmax; s0 += 128) {
        // Load key tile + tile-max |k|
        const float* kp = kb + (size_t)(s0 + tid) * 3;
        float k0 = kp[0], k1 = kp[1], k2 = kp[2];
        skv[tid] = make_float4(k0, k1, k2, 0.f);
        float nk = sqrtf(k0 * k0 + k1 * k1 + k2 * k2);
        #pragma unroll
        for (int o = 16; o; o >>= 1) nk = fmaxf(nk, __shfl_xor_sync(0xffffffffu, nk, o));
        if ((tid & 31) == 0) red[tid >> 5] = nk;
        // Load value tile (2048 float4, 16 per thread)
        const float4* vsrc = (const float4*)(vb + (size_t)s0 * HD);
        float4* vdst = (float4*)&sv[0][0];
        #pragma unroll
        for (int i = 0; i < 16; i++) vdst[tid + i * 128] = vsrc[tid + i * 128];
        __syncthreads();

        const int send = min(128, qi - s0 + 1);
        if (send > 0) {
            const float kmx = fmaxf(fmaxf(red[0], red[1]), fmaxf(red[2], red[3]));
            const float mt = qn * kmx;            // >= every score in this tile
            const float mnew = fmaxf(m, mt);
            const float corr = __expf(m - mnew);
            m = mnew;
            l *= corr;
            #pragma unroll
            for (int d = 0; d < HD; d++) acc[d] *= corr;

            for (int s = 0; s < send; s++) {
                float4 kv = skv[s];
                float sc = q0 * kv.x + q1 * kv.y + q2 * kv.z;
                float p = __expf(sc - m);         // <= 1 by construction
                l += p;
                const float4* vr = (const float4*)sv[s];
                #pragma unroll
                for (int d4 = 0; d4 < 16; d4++) {
                    float4 vv = vr[d4];
                    acc[d4 * 4 + 0] = fmaf(p, vv.x, acc[d4 * 4 + 0]);
                    acc[d4 * 4 + 1] = fmaf(p, vv.y, acc[d4 * 4 + 1]);
                    acc[d4 * 4 + 2] = fmaf(p, vv.z, acc[d4 * 4 + 2]);
                    acc[d4 * 4 + 3] = fmaf(p, vv.w, acc[d4 * 4 + 3]);
                }
            }
        }
        __syncthreads();
    }

    const float inv = 1.f / l;
    const int b = bh >> 4, h = bh & 15;
    float* op = g_ao + ((size_t)(b * Tt + qi)) * Cc + h * HD;
    #pragma unroll
    for (int d4 = 0; d4 < 16; d4++) {
        ((float4*)op)[d4] = make_float4(acc[d4 * 4 + 0] * inv, acc[d4 * 4 + 1] * inv,
                                        acc[d4 * 4 + 2] * inv, acc[d4 * 4 + 3] * inv);
    }
}

// ---------------------------------------------------------------------------
extern "C" void kernel_launch(void* const* d_in, const int* in_sizes, int n_in,
                              void* d_out, int out_size) {
    const float* x     = (const float*)d_in[0];
    const float* wq    = (const float*)d_in[1];
    const float* wk    = (const float*)d_in[2];
    const float* wv    = (const float*)d_in[3];
    const float* wo    = (const float*)d_in[4];
    const float* dirs  = (const float*)d_in[5];
    const float* scale = (const float*)d_in[6];
    float* out = (float*)d_out;

    void *p_v = nullptr, *p_ao = nullptr;
    cudaGetSymbolAddress(&p_v,  g_v);
    cudaGetSymbolAddress(&p_ao, g_ao);

    // 1. QK projection + key transform
    proj_qk_kernel<<<(Bb * Tt) / 8, 128>>>(x, wq, wk, dirs, scale);

    // 2. V projection GEMM (scatter to (b,h,t,64))
    gemm_kernel<true><<<dim3(Cc / 64, (Bb * Tt) / 64), 256>>>(x, wv, (float*)p_v);

    // 3. Flash attention
    attn_kernel<<<dim3(Tt / 128, Bb * Hh), 128>>>();

    // 4. Output projection GEMM
    gemm_kernel<false><<<dim3(Cc / 64, (Bb * Tt) / 64), 256>>>((const float*)p_ao, wo, out);
}

// round 6
// speedup vs baseline: 1.0621x; 1.0621x over previous
#include <cuda_runtime.h>
#include <cuda_bf16.h>

#define Bb 2
#define Tt 2048
#define Cc 1024
#define Hh 16
#define HD 64

typedef unsigned long long ull;

// Packed f32x2 helpers (sm_103a): ptxas never auto-fuses these — must be PTX.
#define FMA2(d, a, b) \
    asm("fma.rn.f32x2 %0, %1, %2, %0;" : "+l"(d) : "l"(a), "l"(b))
#define MUL2_IP(d, a) \
    asm("mul.rn.f32x2 %0, %1, %0;" : "+l"(d) : "l"(a))

__device__ __forceinline__ ull pack2(float lo, float hi) {
    ull r;
    asm("mov.b64 %0, {%1, %2};" : "=l"(r) : "f"(lo), "f"(hi));
    return r;
}

// Scratch (allocation-free rule: __device__ globals)
__device__ float g_q3[(size_t)Bb*Hh*Tt*3];           // (b,h,t,3)
__device__ float g_ka[(size_t)Bb*Hh*Tt*3];           // (b,h,t,3) transformed keys
__device__ float g_v [(size_t)Bb*Hh*Tt*HD];          // (b,h,t,64)
__device__ float g_ao[(size_t)Bb*Tt*Cc];             // (b,t,c) attention output

// ---------------------------------------------------------------------------
// Kernel 1: QK projection + fold (scale*I + d d^T) into K.
// ---------------------------------------------------------------------------
__global__ void proj_qk_kernel(const float* __restrict__ x,
                               const float* __restrict__ wq,
                               const float* __restrict__ wk,
                               const float* __restrict__ dirs,
                               const float* __restrict__ scale_p) {
    __shared__ float xs[8][Cc];
    __shared__ float sk[8][48];
    const int tid = threadIdx.x;                 // 128
    const int rowBase = blockIdx.x * 8;

    {
        const float4* src = (const float4*)(x + (size_t)rowBase * Cc);
        float4* dst = (float4*)&xs[0][0];
        #pragma unroll
        for (int i = tid; i < 8 * Cc / 4; i += 128) dst[i] = src[i];
    }
    __syncthreads();

    if (tid < 96) {
        const int col = tid % 48;
        const float* __restrict__ w = (tid < 48) ? wq : wk;
        float acc[8];
        #pragma unroll
        for (int r = 0; r < 8; r++) acc[r] = 0.f;
        for (int i = 0; i < Cc; i += 4) {
            float w0 = w[(i + 0) * 48 + col];
            float w1 = w[(i + 1) * 48 + col];
            float w2 = w[(i + 2) * 48 + col];
            float w3 = w[(i + 3) * 48 + col];
            #pragma unroll
            for (int r = 0; r < 8; r++) {
                float4 xv = *(const float4*)&xs[r][i];
                acc[r] = fmaf(xv.x, w0, fmaf(xv.y, w1, fmaf(xv.z, w2, fmaf(xv.w, w3, acc[r]))));
            }
        }
        const int h = col / 3, d = col % 3;
        if (tid < 48) {
            #pragma unroll
            for (int r = 0; r < 8; r++) {
                int row = rowBase + r;
                int b = row / Tt, t = row % Tt;
                g_q3[(((size_t)b * Hh + h) * Tt + t) * 3 + d] = acc[r];
            }
        } else {
            #pragma unroll
            for (int r = 0; r < 8; r++) sk[r][col] = acc[r];
        }
    }
    __syncthreads();

    {
        const int r = tid >> 4, h = tid & 15;
        const float d0 = dirs[h * 3 + 0], d1 = dirs[h * 3 + 1], d2 = dirs[h * 3 + 2];
        const float sc = scale_p[0];
        const float k0 = sk[r][3 * h + 0], k1 = sk[r][3 * h + 1], k2 = sk[r][3 * h + 2];
        const float dot = d0 * k0 + d1 * k1 + d2 * k2;
        int row = rowBase + r;
        int b = row / Tt, t = row % Tt;
        size_t base = (((size_t)b * Hh + h) * Tt + t) * 3;
        g_ka[base + 0] = sc * k0 + d0 * dot;
        g_ka[base + 1] = sc * k1 + d1 * dot;
        g_ka[base + 2] = sc * k2 + d2 * dot;
    }
}

// ---------------------------------------------------------------------------
// Kernel 2/4: fp32 GEMM using packed fma.rn.f32x2.
// 128x128 tile, BK=8, 256 threads, 8x8 micro-tile (32 FMA2 per kk).
// A is stored DUPLICATED in smem ((a,a) pairs) so an LDS.64 directly yields
// a broadcast-packed f32x2 operand.
// ---------------------------------------------------------------------------
template <bool SCATTER>
__global__ void gemm_kernel(const float* __restrict__ A,
                            const float* __restrict__ Bw,
                            float* __restrict__ Cout) {
    const int N = Cc;           // 1024
    const int K = Cc;           // 1024
    __shared__ float As2[8][264];   // duplicated: 256 used + 8 pad (bank skew)
    __shared__ float Bs[8][128];

    const int tid = threadIdx.x;
    const int tx = tid % 16;
    const int ty = tid / 16;
    const int rowBase = blockIdx.y * 128;
    const int colBase = blockIdx.x * 128;

    ull acc[8][4];
    #pragma unroll
    for (int i = 0; i < 8; i++)
        #pragma unroll
        for (int j = 0; j < 4; j++) acc[i][j] = 0ULL;

    const int arow = tid >> 1, acol = (tid & 1) * 4;   // A tile 128 rows x 8 k
    const int brow = tid >> 5, bcol = (tid & 31) * 4;  // B tile 8 rows x 128 cols

    for (int k0 = 0; k0 < K; k0 += 8) {
        float4 a = *(const float4*)&A[(size_t)(rowBase + arow) * K + k0 + acol];
        *(float2*)&As2[acol + 0][2 * arow] = make_float2(a.x, a.x);
        *(float2*)&As2[acol + 1][2 * arow] = make_float2(a.y, a.y);
        *(float2*)&As2[acol + 2][2 * arow] = make_float2(a.z, a.z);
        *(float2*)&As2[acol + 3][2 * arow] = make_float2(a.w, a.w);
        *(float4*)&Bs[brow][bcol] = *(const float4*)&Bw[(size_t)(k0 + brow) * N + colBase + bcol];
        __syncthreads();

        #pragma unroll
        for (int kk = 0; kk < 8; kk++) {
            ull ap[8];
            #pragma unroll
            for (int i2 = 0; i2 < 4; i2++) {
                ulonglong2 av = *(const ulonglong2*)&As2[kk][ty * 16 + i2 * 4];
                ap[i2 * 2 + 0] = av.x;
                ap[i2 * 2 + 1] = av.y;
            }
            ulonglong2 b01 = *(const ulonglong2*)&Bs[kk][tx * 8];
            ulonglong2 b23 = *(const ulonglong2*)&Bs[kk][tx * 8 + 4];
            ull bp[4] = {b01.x, b01.y, b23.x, b23.y};
            #pragma unroll
            for (int i = 0; i < 8; i++)
                #pragma unroll
                for (int j = 0; j < 4; j++)
                    FMA2(acc[i][j], ap[i], bp[j]);
        }
        __syncthreads();
    }

    #pragma unroll
    for (int i = 0; i < 8; i++) {
        int m = rowBase + ty * 8 + i;
        #pragma unroll
        for (int j = 0; j < 4; j++) {
            int n = colBase + tx * 8 + j * 2;   // even -> pair stays in one head
            if (SCATTER) {
                int b = m >> 11, t = m & (Tt - 1);
                int h = n >> 6, d = n & (HD - 1);
                *(ull*)&Cout[(((size_t)b * Hh + h) * Tt + t) * HD + d] = acc[i][j];
            } else {
                *(ull*)&Cout[(size_t)m * N + n] = acc[i][j];
            }
        }
    }
}

// ---------------------------------------------------------------------------
// Kernel 3: causal flash attention, d_qk=3 (bias folded into ka), d_v=64.
// 1 thread = 1 query; PV accumulate in packed f32x2 (32 FMA2 per key).
// ---------------------------------------------------------------------------
__global__ void attn_kernel() {
    __shared__ float4 skv[128];        // key tile (k0,k1,k2,pad)
    __shared__ float  sv[128][HD];     // value tile 32KB
    __shared__ float  red[4];

    const int tid = threadIdx.x;       // 128
    const int bh  = blockIdx.y;
    const int qt  = blockIdx.x;
    const int qi  = qt * 128 + tid;

    const float* qp = g_q3 + ((size_t)bh * Tt + qi) * 3;
    const float q0 = qp[0], q1 = qp[1], q2 = qp[2];
    const float qn = sqrtf(q0 * q0 + q1 * q1 + q2 * q2);

    float m = -1e30f, l = 0.f;
    ull acc[32];
    #pragma unroll
    for (int d = 0; d < 32; d++) acc[d] = 0ULL;

    const int kmax = qt * 128 + 127;
    const float* kb = g_ka + (size_t)bh * Tt * 3;
    const float* vb = g_v  + (size_t)bh * Tt * HD;

    for (int s0 = 0; s0 <= kmax; s0 += 128) {
        const float* kp = kb + (size_t)(s0 + tid) * 3;
        float k0 = kp[0], k1 = kp[1], k2 = kp[2];
        skv[tid] = make_float4(k0, k1, k2, 0.f);
        float nk = sqrtf(k0 * k0 + k1 * k1 + k2 * k2);
        #pragma unroll
        for (int o = 16; o; o >>= 1) nk = fmaxf(nk, __shfl_xor_sync(0xffffffffu, nk, o));
        if ((tid & 31) == 0) red[tid >> 5] = nk;
        const float4* vsrc = (const float4*)(vb + (size_t)s0 * HD);
        float4* vdst = (float4*)&sv[0][0];
        #pragma unroll
        for (int i = 0; i < 16; i++) vdst[tid + i * 128] = vsrc[tid + i * 128];
        __syncthreads();

        const int send = min(128, qi - s0 + 1);
        if (send > 0) {
            const float kmx = fmaxf(fmaxf(red[0], red[1]), fmaxf(red[2], red[3]));
            const float mt = qn * kmx;            // Cauchy-Schwarz bound on tile scores
            const float mnew = fmaxf(m, mt);
            const float corr = __expf(m - mnew);
            m = mnew;
            l *= corr;
            const ull cp = pack2(corr, corr);
            #pragma unroll
            for (int d = 0; d < 32; d++) MUL2_IP(acc[d], cp);

            for (int s = 0; s < send; s++) {
                float4 kv = skv[s];
                float sc = fmaf(q0, kv.x, fmaf(q1, kv.y, q2 * kv.z));
                float p = __expf(sc - m);         // <= 1 by construction
                l += p;
                const ull pp = pack2(p, p);
                const ulonglong2* vr = (const ulonglong2*)sv[s];
                #pragma unroll
                for (int j = 0; j < 16; j++) {
                    ulonglong2 vv = vr[j];
                    FMA2(acc[2 * j + 0], pp, vv.x);
                    FMA2(acc[2 * j + 1], pp, vv.y);
                }
            }
        }
        __syncthreads();
    }

    const float inv = 1.f / l;
    const ull ip = pack2(inv, inv);
    #pragma unroll
    for (int d = 0; d < 32; d++) MUL2_IP(acc[d], ip);

    const int b = bh >> 4, h = bh & 15;
    ull* op = (ull*)(g_ao + ((size_t)(b * Tt + qi)) * Cc + h * HD);
    #pragma unroll
    for (int d = 0; d < 32; d++) op[d] = acc[d];
}

// ---------------------------------------------------------------------------
extern "C" void kernel_launch(void* const* d_in, const int* in_sizes, int n_in,
                              void* d_out, int out_size) {
    const float* x     = (const float*)d_in[0];
    const float* wq    = (const float*)d_in[1];
    const float* wk    = (const float*)d_in[2];
    const float* wv    = (const float*)d_in[3];
    const float* wo    = (const float*)d_in[4];
    const float* dirs  = (const float*)d_in[5];
    const float* scale = (const float*)d_in[6];
    float* out = (float*)d_out;

    void *p_v = nullptr, *p_ao = nullptr;
    cudaGetSymbolAddress(&p_v,  g_v);
    cudaGetSymbolAddress(&p_ao, g_ao);

    // 1. QK projection + key transform
    proj_qk_kernel<<<(Bb * Tt) / 8, 128>>>(x, wq, wk, dirs, scale);

    // 2. V projection GEMM (scatter to (b,h,t,64))
    gemm_kernel<true><<<dim3(Cc / 128, (Bb * Tt) / 128), 256>>>(x, wv, (float*)p_v);

    // 3. Flash attention
    attn_kernel<<<dim3(Tt / 128, Bb * Hh), 128>>>();

    // 4. Output projection GEMM
    gemm_kernel<false><<<dim3(Cc / 128, (Bb * Tt) / 128), 256>>>((const float*)p_ao, wo, out);
}

// round 8
// speedup vs baseline: 1.1868x; 1.1175x over previous
#include <cuda_runtime.h>
#include <cuda_bf16.h>

#define Bb 2
#define Tt 2048
#define Cc 1024
#define Hh 16
#define HD 64

typedef unsigned long long ull;

// Packed f32x2 helpers (sm_103a): only reachable via PTX fma.rn.f32x2.
#define FMA2(d, a, b) \
    asm("fma.rn.f32x2 %0, %1, %2, %0;" : "+l"(d) : "l"(a), "l"(b))
#define MUL2_IP(d, a) \
    asm("mul.rn.f32x2 %0, %1, %0;" : "+l"(d) : "l"(a))

__device__ __forceinline__ ull pack2(float lo, float hi) {
    ull r;
    asm("mov.b64 %0, {%1, %2};" : "=l"(r) : "f"(lo), "f"(hi));
    return r;
}
__device__ __forceinline__ void unpack2(ull v, float& lo, float& hi) {
    asm("mov.b64 {%0, %1}, %2;" : "=f"(lo), "=f"(hi) : "l"(v));
}

// Scratch (allocation-free rule: __device__ globals)
__device__ float g_q3[(size_t)Bb*Hh*Tt*3];           // (b,h,t,3)
__device__ float g_ka[(size_t)Bb*Hh*Tt*3];           // (b,h,t,3) transformed keys
__device__ float g_v [(size_t)Bb*Hh*Tt*HD];          // (b,h,t,64)
__device__ float g_ao[(size_t)Bb*Tt*Cc];             // (b,t,c) attention output

// ---------------------------------------------------------------------------
// Kernel 1: QK projection + fold (scale*I + d d^T) into K.
// ---------------------------------------------------------------------------
__global__ void proj_qk_kernel(const float* __restrict__ x,
                               const float* __restrict__ wq,
                               const float* __restrict__ wk,
                               const float* __restrict__ dirs,
                               const float* __restrict__ scale_p) {
    __shared__ float xs[8][Cc];
    __shared__ float sk[8][48];
    const int tid = threadIdx.x;                 // 128
    const int rowBase = blockIdx.x * 8;

    {
        const float4* src = (const float4*)(x + (size_t)rowBase * Cc);
        float4* dst = (float4*)&xs[0][0];
        #pragma unroll
        for (int i = tid; i < 8 * Cc / 4; i += 128) dst[i] = src[i];
    }
    __syncthreads();

    if (tid < 96) {
        const int col = tid % 48;
        const float* __restrict__ w = (tid < 48) ? wq : wk;
        float acc[8];
        #pragma unroll
        for (int r = 0; r < 8; r++) acc[r] = 0.f;
        for (int i = 0; i < Cc; i += 4) {
            float w0 = w[(i + 0) * 48 + col];
            float w1 = w[(i + 1) * 48 + col];
            float w2 = w[(i + 2) * 48 + col];
            float w3 = w[(i + 3) * 48 + col];
            #pragma unroll
            for (int r = 0; r < 8; r++) {
                float4 xv = *(const float4*)&xs[r][i];
                acc[r] = fmaf(xv.x, w0, fmaf(xv.y, w1, fmaf(xv.z, w2, fmaf(xv.w, w3, acc[r]))));
            }
        }
        const int h = col / 3, d = col % 3;
        if (tid < 48) {
            #pragma unroll
            for (int r = 0; r < 8; r++) {
                int row = rowBase + r;
                int b = row / Tt, t = row % Tt;
                g_q3[(((size_t)b * Hh + h) * Tt + t) * 3 + d] = acc[r];
            }
        } else {
            #pragma unroll
            for (int r = 0; r < 8; r++) sk[r][col] = acc[r];
        }
    }
    __syncthreads();

    {
        const int r = tid >> 4, h = tid & 15;
        const float d0 = dirs[h * 3 + 0], d1 = dirs[h * 3 + 1], d2 = dirs[h * 3 + 2];
        const float sc = scale_p[0];
        const float k0 = sk[r][3 * h + 0], k1 = sk[r][3 * h + 1], k2 = sk[r][3 * h + 2];
        const float dot = d0 * k0 + d1 * k1 + d2 * k2;
        int row = rowBase + r;
        int b = row / Tt, t = row % Tt;
        size_t base = (((size_t)b * Hh + h) * Tt + t) * 3;
        g_ka[base + 0] = sc * k0 + d0 * dot;
        g_ka[base + 1] = sc * k1 + d1 * dot;
        g_ka[base + 2] = sc * k2 + d2 * dot;
    }
}

// ---------------------------------------------------------------------------
// Kernel 2/4: fp32 GEMM with packed fma.rn.f32x2.
// 64x64 tile, BK=8, 64 threads, grid=1024 (fine-grained -> balanced waves).
// Micro-tile 8 rows x 8 cols as 4 ROW-PAIRS x 8 cols:
//   A operand = natural (r,r+1) pair straight from k-major smem (no movs),
//   B operand = (b_j,b_j) via mov.b64. 2.0 B smem / FMA2 -> FMA2-bound.
// ---------------------------------------------------------------------------
template <bool SCATTER>
__global__ void __launch_bounds__(64, 8)
gemm_kernel(const float* __restrict__ A,
            const float* __restrict__ Bw,
            float* __restrict__ Cout) {
    const int N = Cc;           // 1024
    const int K = Cc;           // 1024
    __shared__ float As[8][64];    // k-major: As[k][row]
    __shared__ float Bs[8][72];    // 16B pad per 128B: pos = c + (c>>5)*4

    const int tid = threadIdx.x;   // 64
    const int tx = tid & 7;
    const int ty = tid >> 3;
    const int rowBase = blockIdx.y * 64;
    const int colBase = blockIdx.x * 64;

    ull acc[4][8];
    #pragma unroll
    for (int p = 0; p < 4; p++)
        #pragma unroll
        for (int j = 0; j < 8; j++) acc[p][j] = 0ULL;

    const int bRow = tid >> 3;               // 0..7 (k within tile)
    const int bColL = (tid & 7) * 8;         // logical col base for B fill
    const int bPos = bColL + ((bColL >> 5) << 2);
    const int rb = tx * 8 + ((tx >> 2) << 2);   // padded read base for B

    const float* aSrc = A + (size_t)(rowBase + tid) * K;
    const float* bSrc = Bw + (size_t)bRow * N + colBase + bColL;

    for (int k0 = 0; k0 < K; k0 += 8) {
        float4 a0 = *(const float4*)(aSrc + k0 + 0);
        float4 a1 = *(const float4*)(aSrc + k0 + 4);
        As[0][tid] = a0.x; As[1][tid] = a0.y; As[2][tid] = a0.z; As[3][tid] = a0.w;
        As[4][tid] = a1.x; As[5][tid] = a1.y; As[6][tid] = a1.z; As[7][tid] = a1.w;
        float4 b0 = *(const float4*)(bSrc + (size_t)k0 * N);
        float4 b1 = *(const float4*)(bSrc + (size_t)k0 * N + 4);
        *(float4*)&Bs[bRow][bPos + 0] = b0;
        *(float4*)&Bs[bRow][bPos + 4] = b1;
        __syncthreads();

        #pragma unroll
        for (int kk = 0; kk < 8; kk++) {
            // A: 8 rows = 4 natural pairs (adjacent rows contiguous in k-major)
            ulonglong2 av0 = *(const ulonglong2*)&As[kk][ty * 8 + 0];
            ulonglong2 av1 = *(const ulonglong2*)&As[kk][ty * 8 + 4];
            ull ap[4] = {av0.x, av0.y, av1.x, av1.y};
            float4 bv0 = *(const float4*)&Bs[kk][rb + 0];
            float4 bv1 = *(const float4*)&Bs[kk][rb + 4];
            ull bd[8];
            bd[0] = pack2(bv0.x, bv0.x); bd[1] = pack2(bv0.y, bv0.y);
            bd[2] = pack2(bv0.z, bv0.z); bd[3] = pack2(bv0.w, bv0.w);
            bd[4] = pack2(bv1.x, bv1.x); bd[5] = pack2(bv1.y, bv1.y);
            bd[6] = pack2(bv1.z, bv1.z); bd[7] = pack2(bv1.w, bv1.w);
            #pragma unroll
            for (int p = 0; p < 4; p++)
                #pragma unroll
                for (int j = 0; j < 8; j++)
                    FMA2(acc[p][j], ap[p], bd[j]);
        }
        __syncthreads();
    }

    #pragma unroll
    for (int p = 0; p < 4; p++) {
        int m0 = rowBase + ty * 8 + 2 * p;
        #pragma unroll
        for (int j = 0; j < 8; j++) {
            int n = colBase + tx * 8 + j;
            float lo, hi;
            unpack2(acc[p][j], lo, hi);
            if (SCATTER) {
                int h = n >> 6, d = n & (HD - 1);
                int b0i = m0 >> 11, t0 = m0 & (Tt - 1);
                int b1i = (m0 + 1) >> 11, t1 = (m0 + 1) & (Tt - 1);
                g_v[(((size_t)b0i * Hh + h) * Tt + t0) * HD + d] = lo;
                g_v[(((size_t)b1i * Hh + h) * Tt + t1) * HD + d] = hi;
            } else {
                Cout[(size_t)m0 * N + n] = lo;
                Cout[(size_t)(m0 + 1) * N + n] = hi;
            }
        }
    }
}

// ---------------------------------------------------------------------------
// Kernel 3: causal flash attention, d_qk=3 (bias folded into ka), d_v=64.
// 2 threads per query (each owns 32 of 64 d-components, interleaved by 16B
// chunk so the halves never bank-collide). p/l computed redundantly per half.
// ---------------------------------------------------------------------------
__global__ void __launch_bounds__(256)
attn_kernel() {
    __shared__ float4 skv[128];        // key tile (k0,k1,k2,pad)
    __shared__ float  sv[128][HD];     // value tile 32KB
    __shared__ float  red[4];

    const int tid  = threadIdx.x;      // 256
    const int q    = tid >> 1;         // query within tile: 0..127
    const int half = tid & 1;          // d-half owner
    const int bh   = blockIdx.y;
    const int qt   = gridDim.x - 1 - blockIdx.x;   // heavy tiles first
    const int qi   = qt * 128 + q;

    const float* qp = g_q3 + ((size_t)bh * Tt + qi) * 3;
    const float q0 = qp[0], q1 = qp[1], q2 = qp[2];
    const float qn = sqrtf(q0 * q0 + q1 * q1 + q2 * q2);

    float m = -1e30f, l = 0.f;
    ull acc[16];                        // 8 chunks x 2 ull = 32 floats
    #pragma unroll
    for (int d = 0; d < 16; d++) acc[d] = 0ULL;

    const int kmax = qt * 128 + 127;
    const float* kb = g_ka + (size_t)bh * Tt * 3;
    const float* vb = g_v  + (size_t)bh * Tt * HD;

    for (int s0 = 0; s0 <= kmax; s0 += 128) {
        // Key tile + per-tile max |k| (first 4 warps)
        if (tid < 128) {
            const float* kp = kb + (size_t)(s0 + tid) * 3;
            float k0 = kp[0], k1 = kp[1], k2 = kp[2];
            skv[tid] = make_float4(k0, k1, k2, 0.f);
            float nk = sqrtf(k0 * k0 + k1 * k1 + k2 * k2);
            #pragma unroll
            for (int o = 16; o; o >>= 1) nk = fmaxf(nk, __shfl_xor_sync(0xffffffffu, nk, o));
            if ((tid & 31) == 0) red[tid >> 5] = nk;
        }
        // Value tile: 2048 float4 / 256 threads
        {
            const float4* vsrc = (const float4*)(vb + (size_t)s0 * HD);
            float4* vdst = (float4*)&sv[0][0];
            #pragma unroll
            for (int i = 0; i < 8; i++) vdst[tid + i * 256] = vsrc[tid + i * 256];
        }
        __syncthreads();

        const int send = min(128, qi - s0 + 1);
        if (send > 0) {
            const float kmx = fmaxf(fmaxf(red[0], red[1]), fmaxf(red[2], red[3]));
            const float mnew = fmaxf(m, qn * kmx);   // Cauchy-Schwarz tile bound
            const float corr = __expf(m - mnew);
            m = mnew;
            l *= corr;
            const ull cp = pack2(corr, corr);
            #pragma unroll
            for (int d = 0; d < 16; d++) MUL2_IP(acc[d], cp);

            for (int s = 0; s < send; s++) {
                float4 kv = skv[s];
                float sc = fmaf(q0, kv.x, fmaf(q1, kv.y, q2 * kv.z));
                float p = __expf(sc - m);            // <= 1 by construction
                l += p;
                const ull pp = pack2(p, p);
                const ulonglong2* vr = (const ulonglong2*)sv[s];  // 16 x 16B chunks
                #pragma unroll
                for (int j = 0; j < 8; j++) {
                    ulonglong2 vv = vr[2 * j + half];            // interleaved halves
                    FMA2(acc[2 * j + 0], pp, vv.x);
                    FMA2(acc[2 * j + 1], pp, vv.y);
                }
            }
        }
        __syncthreads();
    }

    const float inv = 1.f / l;
    const ull ip = pack2(inv, inv);
    const int b = bh >> 4, h = bh & 15;
    float4* op = (float4*)(g_ao + ((size_t)(b * Tt + qi)) * Cc + h * HD);
    #pragma unroll
    for (int j = 0; j < 8; j++) {
        ull u0 = acc[2 * j + 0], u1 = acc[2 * j + 1];
        MUL2_IP(u0, ip);
        MUL2_IP(u1, ip);
        float4 o;
        unpack2(u0, o.x, o.y);
        unpack2(u1, o.z, o.w);
        op[2 * j + half] = o;
    }
}

// ---------------------------------------------------------------------------
extern "C" void kernel_launch(void* const* d_in, const int* in_sizes, int n_in,
                              void* d_out, int out_size) {
    const float* x     = (const float*)d_in[0];
    const float* wq    = (const float*)d_in[1];
    const float* wk    = (const float*)d_in[2];
    const float* wv    = (const float*)d_in[3];
    const float* wo    = (const float*)d_in[4];
    const float* dirs  = (const float*)d_in[5];
    const float* scale = (const float*)d_in[6];
    float* out = (float*)d_out;

    void *p_ao = nullptr;
    cudaGetSymbolAddress(&p_ao, g_ao);

    // 1. QK projection + key transform
    proj_qk_kernel<<<(Bb * Tt) / 8, 128>>>(x, wq, wk, dirs, scale);

    // 2. V projection GEMM (scatter to (b,h,t,64) via template path)
    gemm_kernel<true><<<dim3(Cc / 64, (Bb * Tt) / 64), 64>>>(x, wv, nullptr);

    // 3. Flash attention
    attn_kernel<<<dim3(Tt / 128, Bb * Hh), 256>>>();

    // 4. Output projection GEMM
    gemm_kernel<false><<<dim3(Cc / 64, (Bb * Tt) / 64), 64>>>((const float*)p_ao, wo, out);
}

// round 10
// speedup vs baseline: 1.2410x; 1.0457x over previous
#include <cuda_runtime.h>
#include <cuda_bf16.h>
#include <cstdint>

#define Bb 2
#define Tt 2048
#define Cc 1024
#define Hh 16
#define HD 64

typedef unsigned long long ull;
typedef unsigned int uint32;

// Packed f32x2 helpers (sm_103a): only reachable via PTX fma.rn.f32x2.
#define FMA2(d, a, b) \
    asm("fma.rn.f32x2 %0, %1, %2, %0;" : "+l"(d) : "l"(a), "l"(b))
#define MUL2_IP(d, a) \
    asm("mul.rn.f32x2 %0, %1, %0;" : "+l"(d) : "l"(a))

__device__ __forceinline__ ull pack2(float lo, float hi) {
    ull r;
    asm("mov.b64 %0, {%1, %2};" : "=l"(r) : "f"(lo), "f"(hi));
    return r;
}
__device__ __forceinline__ void unpack2(ull v, float& lo, float& hi) {
    asm("mov.b64 {%0, %1}, %2;" : "=f"(lo), "=f"(hi) : "l"(v));
}
__device__ __forceinline__ void cpasync16(uint32 dst, const void* src) {
    asm volatile("cp.async.cg.shared.global [%0], [%1], 16;" :: "r"(dst), "l"(src) : "memory");
}
__device__ __forceinline__ void cpasync_commit() {
    asm volatile("cp.async.commit_group;" ::: "memory");
}
__device__ __forceinline__ void cpasync_wait0() {
    asm volatile("cp.async.wait_group 0;" ::: "memory");
}

// Scratch (allocation-free rule: __device__ globals)
__device__ float g_q3[(size_t)Bb*Hh*Tt*3];           // (b,h,t,3)
__device__ float g_ka[(size_t)Bb*Hh*Tt*3];           // (b,h,t,3) transformed keys
__device__ float g_v [(size_t)Bb*Hh*Tt*HD];          // (b,h,t,64)
__device__ float g_ao[(size_t)Bb*Tt*Cc];             // (b,t,c) attention output

// ---------------------------------------------------------------------------
// Kernel 1: QK projection + fold (scale*I + d d^T) into K.
// ---------------------------------------------------------------------------
__global__ void proj_qk_kernel(const float* __restrict__ x,
                               const float* __restrict__ wq,
                               const float* __restrict__ wk,
                               const float* __restrict__ dirs,
                               const float* __restrict__ scale_p) {
    __shared__ float xs[8][Cc];
    __shared__ float sk[8][48];
    const int tid = threadIdx.x;                 // 128
    const int rowBase = blockIdx.x * 8;

    {
        const float4* src = (const float4*)(x + (size_t)rowBase * Cc);
        float4* dst = (float4*)&xs[0][0];
        #pragma unroll
        for (int i = tid; i < 8 * Cc / 4; i += 128) dst[i] = src[i];
    }
    __syncthreads();

    if (tid < 96) {
        const int col = tid % 48;
        const float* __restrict__ w = (tid < 48) ? wq : wk;
        float acc[8];
        #pragma unroll
        for (int r = 0; r < 8; r++) acc[r] = 0.f;
        for (int i = 0; i < Cc; i += 4) {
            float w0 = w[(i + 0) * 48 + col];
            float w1 = w[(i + 1) * 48 + col];
            float w2 = w[(i + 2) * 48 + col];
            float w3 = w[(i + 3) * 48 + col];
            #pragma unroll
            for (int r = 0; r < 8; r++) {
                float4 xv = *(const float4*)&xs[r][i];
                acc[r] = fmaf(xv.x, w0, fmaf(xv.y, w1, fmaf(xv.z, w2, fmaf(xv.w, w3, acc[r]))));
            }
        }
        const int h = col / 3, d = col % 3;
        if (tid < 48) {
            #pragma unroll
            for (int r = 0; r < 8; r++) {
                int row = rowBase + r;
                int b = row / Tt, t = row % Tt;
                g_q3[(((size_t)b * Hh + h) * Tt + t) * 3 + d] = acc[r];
            }
        } else {
            #pragma unroll
            for (int r = 0; r < 8; r++) sk[r][col] = acc[r];
        }
    }
    __syncthreads();

    {
        const int r = tid >> 4, h = tid & 15;
        const float d0 = dirs[h * 3 + 0], d1 = dirs[h * 3 + 1], d2 = dirs[h * 3 + 2];
        const float sc = scale_p[0];
        const float k0 = sk[r][3 * h + 0], k1 = sk[r][3 * h + 1], k2 = sk[r][3 * h + 2];
        const float dot = d0 * k0 + d1 * k1 + d2 * k2;
        int row = rowBase + r;
        int b = row / Tt, t = row % Tt;
        size_t base = (((size_t)b * Hh + h) * Tt + t) * 3;
        g_ka[base + 0] = sc * k0 + d0 * dot;
        g_ka[base + 1] = sc * k1 + d1 * dot;
        g_ka[base + 2] = sc * k2 + d2 * dot;
    }
}

// ---------------------------------------------------------------------------
// Kernel 2/4: fp32 GEMM with packed fma.rn.f32x2, double-buffered pipeline.
// 64x64 tile, BK=8, 64 threads, grid=1024 (balanced waves).
// B prefetch: cp.async.cg (no reg staging); A prefetch: LDG->regs, STS after
// compute (transpose needed). One __syncthreads per k-iteration.
// ---------------------------------------------------------------------------
template <bool SCATTER>
__global__ void __launch_bounds__(64, 7)
gemm_kernel(const float* __restrict__ A,
            const float* __restrict__ Bw,
            float* __restrict__ Cout) {
    const int N = Cc;           // 1024
    const int K = Cc;           // 1024
    __shared__ float As[2][8][64];    // k-major: As[buf][k][row]
    __shared__ float Bs[2][8][72];    // 16B pad per 128B

    const int tid = threadIdx.x;   // 64
    const int tx = tid & 7;
    const int ty = tid >> 3;
    const int rowBase = blockIdx.y * 64;
    const int colBase = blockIdx.x * 64;

    ull acc[4][8];
    #pragma unroll
    for (int p = 0; p < 4; p++)
        #pragma unroll
        for (int j = 0; j < 8; j++) acc[p][j] = 0ULL;

    const int bRow = tid >> 3;               // k within B tile
    const int bColL = (tid & 7) * 8;
    const int bPos = bColL + ((bColL >> 5) << 2);
    const int rb = tx * 8 + ((tx >> 2) << 2);   // padded read base for B

    const float* aSrc = A + (size_t)(rowBase + tid) * K;
    const float* bSrc = Bw + (size_t)bRow * N + colBase + bColL;

    uint32 bDst0 = (uint32)__cvta_generic_to_shared(&Bs[0][bRow][bPos]);
    uint32 bDst1 = (uint32)__cvta_generic_to_shared(&Bs[1][bRow][bPos]);

    // ---- prologue: fill buffer 0 ----
    {
        float4 a0 = *(const float4*)(aSrc + 0);
        float4 a1 = *(const float4*)(aSrc + 4);
        cpasync16(bDst0, bSrc);
        cpasync16(bDst0 + 16, bSrc + 4);
        cpasync_commit();
        As[0][0][tid] = a0.x; As[0][1][tid] = a0.y;
        As[0][2][tid] = a0.z; As[0][3][tid] = a0.w;
        As[0][4][tid] = a1.x; As[0][5][tid] = a1.y;
        As[0][6][tid] = a1.z; As[0][7][tid] = a1.w;
        cpasync_wait0();
    }
    __syncthreads();

    for (int k0 = 0; k0 < K; k0 += 8) {
        const int cur = (k0 >> 3) & 1;
        const int nxt = cur ^ 1;
        const bool has = (k0 + 8) < K;

        // Prefetch next iteration: B via cp.async, A via LDG (in flight
        // through the compute block below).
        float4 n0, n1;
        if (has) {
            uint32 bDstN = nxt ? bDst1 : bDst0;
            cpasync16(bDstN, bSrc + (size_t)(k0 + 8) * N);
            cpasync16(bDstN + 16, bSrc + (size_t)(k0 + 8) * N + 4);
            cpasync_commit();
            n0 = *(const float4*)(aSrc + k0 + 8);
            n1 = *(const float4*)(aSrc + k0 + 12);
        }

        #pragma unroll
        for (int kk = 0; kk < 8; kk++) {
            ulonglong2 av0 = *(const ulonglong2*)&As[cur][kk][ty * 8 + 0];
            ulonglong2 av1 = *(const ulonglong2*)&As[cur][kk][ty * 8 + 4];
            ull ap[4] = {av0.x, av0.y, av1.x, av1.y};
            float4 bv0 = *(const float4*)&Bs[cur][kk][rb + 0];
            float4 bv1 = *(const float4*)&Bs[cur][kk][rb + 4];
            ull bd[8];
            bd[0] = pack2(bv0.x, bv0.x); bd[1] = pack2(bv0.y, bv0.y);
            bd[2] = pack2(bv0.z, bv0.z); bd[3] = pack2(bv0.w, bv0.w);
            bd[4] = pack2(bv1.x, bv1.x); bd[5] = pack2(bv1.y, bv1.y);
            bd[6] = pack2(bv1.z, bv1.z); bd[7] = pack2(bv1.w, bv1.w);
            #pragma unroll
            for (int p = 0; p < 4; p++)
                #pragma unroll
                for (int j = 0; j < 8; j++)
                    FMA2(acc[p][j], ap[p], bd[j]);
        }

        if (has) {
            As[nxt][0][tid] = n0.x; As[nxt][1][tid] = n0.y;
            As[nxt][2][tid] = n0.z; As[nxt][3][tid] = n0.w;
            As[nxt][4][tid] = n1.x; As[nxt][5][tid] = n1.y;
            As[nxt][6][tid] = n1.z; As[nxt][7][tid] = n1.w;
            cpasync_wait0();
            __syncthreads();
        }
    }

    #pragma unroll
    for (int p = 0; p < 4; p++) {
        int m0 = rowBase + ty * 8 + 2 * p;
        #pragma unroll
        for (int j = 0; j < 8; j++) {
            int n = colBase + tx * 8 + j;
            float lo, hi;
            unpack2(acc[p][j], lo, hi);
            if (SCATTER) {
                int h = n >> 6, d = n & (HD - 1);
                int b0i = m0 >> 11, t0 = m0 & (Tt - 1);
                int b1i = (m0 + 1) >> 11, t1 = (m0 + 1) & (Tt - 1);
                g_v[(((size_t)b0i * Hh + h) * Tt + t0) * HD + d] = lo;
                g_v[(((size_t)b1i * Hh + h) * Tt + t1) * HD + d] = hi;
            } else {
                Cout[(size_t)m0 * N + n] = lo;
                Cout[(size_t)(m0 + 1) * N + n] = hi;
            }
        }
    }
}

// ---------------------------------------------------------------------------
// Kernel 3: causal flash attention, d_qk=3 (bias folded into ka), d_v=64.
// 2 threads per query (32 d-components each, 16B-interleaved halves).
// ---------------------------------------------------------------------------
__global__ void __launch_bounds__(256)
attn_kernel() {
    __shared__ float4 skv[128];        // key tile (k0,k1,k2,pad)
    __shared__ float  sv[128][HD];     // value tile 32KB
    __shared__ float  red[4];

    const int tid  = threadIdx.x;      // 256
    const int q    = tid >> 1;         // query within tile
    const int half = tid & 1;          // d-half owner
    const int bh   = blockIdx.y;
    const int qt   = gridDim.x - 1 - blockIdx.x;   // heavy tiles first
    const int qi   = qt * 128 + q;

    const float* qp = g_q3 + ((size_t)bh * Tt + qi) * 3;
    const float q0 = qp[0], q1 = qp[1], q2 = qp[2];
    const float qn = sqrtf(q0 * q0 + q1 * q1 + q2 * q2);

    float m = -1e30f, l = 0.f;
    ull acc[16];
    #pragma unroll
    for (int d = 0; d < 16; d++) acc[d] = 0ULL;

    const int kmax = qt * 128 + 127;
    const float* kb = g_ka + (size_t)bh * Tt * 3;
    const float* vb = g_v  + (size_t)bh * Tt * HD;

    for (int s0 = 0; s0 <= kmax; s0 += 128) {
        if (tid < 128) {
            const float* kp = kb + (size_t)(s0 + tid) * 3;
            float k0 = kp[0], k1 = kp[1], k2 = kp[2];
            skv[tid] = make_float4(k0, k1, k2, 0.f);
            float nk = sqrtf(k0 * k0 + k1 * k1 + k2 * k2);
            #pragma unroll
            for (int o = 16; o; o >>= 1) nk = fmaxf(nk, __shfl_xor_sync(0xffffffffu, nk, o));
            if ((tid & 31) == 0) red[tid >> 5] = nk;
        }
        {
            const float4* vsrc = (const float4*)(vb + (size_t)s0 * HD);
            float4* vdst = (float4*)&sv[0][0];
            #pragma unroll
            for (int i = 0; i < 8; i++) vdst[tid + i * 256] = vsrc[tid + i * 256];
        }
        __syncthreads();

        const int send = min(128, qi - s0 + 1);
        if (send > 0) {
            const float kmx = fmaxf(fmaxf(red[0], red[1]), fmaxf(red[2], red[3]));
            const float mnew = fmaxf(m, qn * kmx);   // Cauchy-Schwarz tile bound
            const float corr = __expf(m - mnew);
            m = mnew;
            l *= corr;
            const ull cp = pack2(corr, corr);
            #pragma unroll
            for (int d = 0; d < 16; d++) MUL2_IP(acc[d], cp);

            for (int s = 0; s < send; s++) {
                float4 kv = skv[s];
                float sc = fmaf(q0, kv.x, fmaf(q1, kv.y, q2 * kv.z));
                float p = __expf(sc - m);            // <= 1 by construction
                l += p;
                const ull pp = pack2(p, p);
                const ulonglong2* vr = (const ulonglong2*)sv[s];
                #pragma unroll
                for (int j = 0; j < 8; j++) {
                    ulonglong2 vv = vr[2 * j + half];
                    FMA2(acc[2 * j + 0], pp, vv.x);
                    FMA2(acc[2 * j + 1], pp, vv.y);
                }
            }
        }
        __syncthreads();
    }

    const float inv = 1.f / l;
    const ull ip = pack2(inv, inv);
    const int b = bh >> 4, h = bh & 15;
    float4* op = (float4*)(g_ao + ((size_t)(b * Tt + qi)) * Cc + h * HD);
    #pragma unroll
    for (int j = 0; j < 8; j++) {
        ull u0 = acc[2 * j + 0], u1 = acc[2 * j + 1];
        MUL2_IP(u0, ip);
        MUL2_IP(u1, ip);
        float4 o;
        unpack2(u0, o.x, o.y);
        unpack2(u1, o.z, o.w);
        op[2 * j + half] = o;
    }
}

// ---------------------------------------------------------------------------
extern "C" void kernel_launch(void* const* d_in, const int* in_sizes, int n_in,
                              void* d_out, int out_size) {
    const float* x     = (const float*)d_in[0];
    const float* wq    = (const float*)d_in[1];
    const float* wk    = (const float*)d_in[2];
    const float* wv    = (const float*)d_in[3];
    const float* wo    = (const float*)d_in[4];
    const float* dirs  = (const float*)d_in[5];
    const float* scale = (const float*)d_in[6];
    float* out = (float*)d_out;

    void *p_ao = nullptr;
    cudaGetSymbolAddress(&p_ao, g_ao);

    // 1. QK projection + key transform
    proj_qk_kernel<<<(Bb * Tt) / 8, 128>>>(x, wq, wk, dirs, scale);

    // 2. V projection GEMM (scatter to (b,h,t,64))
    gemm_kernel<true><<<dim3(Cc / 64, (Bb * Tt) / 64), 64>>>(x, wv, nullptr);

    // 3. Flash attention
    attn_kernel<<<dim3(Tt / 128, Bb * Hh), 256>>>();

    // 4. Output projection GEMM
    gemm_kernel<false><<<dim3(Cc / 64, (Bb * Tt) / 64), 64>>>((const float*)p_ao, wo, out);
}